// round 2
// baseline (speedup 1.0000x reference)
#include <cuda_runtime.h>
#include <math.h>

#define NB   64
#define IMG  384
#define CIN  3
#define PS   16
#define DM   96
#define DS   16
#define DI   96
#define HP   24
#define NT   576
#define NR   (NB*NT)          // 36864 token rows
#define NPIX (NB*CIN*IMG*IMG) // 28311552

// ---------------- scratch (device globals; no allocs allowed) ----------------
static __device__ float g_tmp[NPIX];       // horizontal blur sums
static __device__ float g_xl[NPIX];        // preprocessed image
static __device__ float g_tokens[NR*DM];
static __device__ float g_vis[NR];
static __device__ float g_gate[NR*DM];
static __device__ float g_xz[NR*2*DI];     // [row][0:96]=xin, [96:192]=z
static __device__ float g_xs[NR*DI];
static __device__ float g_proj[NR*38];     // dt_raw(6) | B(16) | C(16)
static __device__ float g_dt[NR*DI];
static __device__ float g_yg[NR*DI];

__device__ __forceinline__ float sigm_(float x){ return 1.f/(1.f+__expf(-x)); }
__device__ __forceinline__ float silu_(float x){ return x/(1.f+__expf(-x)); }
__device__ __forceinline__ float softplus_(float x){ return (x>20.f)? x : log1pf(__expf(x)); }

// ---------------- 1) separable 5x5 box blur + log contrast ----------------
__global__ void k_blur_h(const float* __restrict__ x){
    int idx = blockIdx.x*blockDim.x + threadIdx.x;
    int xx  = idx % IMG;
    const float* row = x + (idx - xx);
    float s = 0.f;
    #pragma unroll
    for (int d=-2; d<=2; d++){ int c = xx+d; if (c>=0 && c<IMG) s += row[c]; }
    g_tmp[idx] = s;
}

__global__ void k_blur_v(const float* __restrict__ x){
    int idx = blockIdx.x*blockDim.x + threadIdx.x;
    int xx  = idx % IMG;
    int y   = (idx/IMG) % IMG;
    int bc  = idx/(IMG*IMG);
    float s = 0.f;
    #pragma unroll
    for (int d=-2; d<=2; d++){
        int yy = y+d;
        if (yy>=0 && yy<IMG) s += g_tmp[(bc*IMG+yy)*IMG + xx];
    }
    float bl = s*(1.f/25.f);
    float xv = x[idx];
    g_xl[idx] = log1pf(fmaxf(xv,0.f)) - log1pf(fmaxf(bl,0.f));
}

// ---------------- 2) patch embed: implicit GEMM (36864 x 768) @ (768 x 96) ----------------
// block: 64 patches x 96 dm, 256 threads, thread tile 4p x 6d
__global__ void k_patch(const float* __restrict__ Wpe, const float* __restrict__ bpe){
    __shared__ float As[64][17];
    __shared__ float Bs[16][97];
    int tid = threadIdx.x;
    int tx  = tid & 15, ty = tid >> 4;
    int pbase = blockIdx.x * 64;

    int rb[4];
    #pragma unroll
    for (int r=0;r<4;r++){
        int p  = (tid + 256*r) >> 4;
        int gp = pbase + p;
        int b  = gp / NT; int n = gp % NT;
        int ph = n / HP;  int pw = n % HP;
        rb[r] = ((b*CIN)*IMG + ph*PS)*IMG + pw*PS;
    }
    int jld = tid & 15;

    float acc[4][6];
    #pragma unroll
    for (int i=0;i<4;i++)
        #pragma unroll
        for (int j=0;j<6;j++) acc[i][j]=0.f;

    for (int kc=0; kc<48; kc++){
        int c = kc >> 4; int ii = kc & 15;
        #pragma unroll
        for (int r=0;r<4;r++){
            int p = (tid + 256*r) >> 4;
            As[p][jld] = g_xl[rb[r] + c*IMG*IMG + ii*IMG + jld];
        }
        #pragma unroll
        for (int r=0;r<6;r++){
            int idx = tid + 256*r;
            int d = idx >> 4; int j = idx & 15;
            Bs[j][d] = Wpe[d*768 + kc*16 + j];
        }
        __syncthreads();
        #pragma unroll
        for (int k=0;k<16;k++){
            float bv[6], av[4];
            #pragma unroll
            for (int j=0;j<6;j++) bv[j] = Bs[k][tx + 16*j];
            #pragma unroll
            for (int i=0;i<4;i++) av[i] = As[ty + 16*i][k];
            #pragma unroll
            for (int i=0;i<4;i++)
                #pragma unroll
                for (int j=0;j<6;j++) acc[i][j] = fmaf(av[i], bv[j], acc[i][j]);
        }
        __syncthreads();
    }
    #pragma unroll
    for (int i=0;i<4;i++)
        #pragma unroll
        for (int j=0;j<6;j++){
            int gp = pbase + ty + 16*i;
            int d  = tx + 16*j;
            g_tokens[gp*DM + d] = acc[i][j] + bpe[d];
        }
}

// ---------------- 3) row GEMM with fused LN + epilogues ----------------
// mode 0: tokens -> LN(dn) (written back) ; gate = sigmoid(LN @ W_gate + b) ; vis from raw row
// mode 1: LN(ln)(tokens) @ W_in -> g_xz[colbase..colbase+96)
// mode 2: g_yg @ W_out ; tokens += out * gate
__global__ void k_rowgemm(int mode,
                          const float* __restrict__ W, int wstride,
                          const float* __restrict__ lng, const float* __restrict__ lnb,
                          const float* __restrict__ Wvis, const float* __restrict__ bvis,
                          const float* __restrict__ bgate){
    __shared__ float As[64][97];
    __shared__ float Bs[32][97];
    int tid = threadIdx.x;
    int tx = tid & 15, ty = tid >> 4;
    int rowbase = blockIdx.x * 64;
    int colbase = blockIdx.y * 96;

    const float* Asrc = (mode==2) ? g_yg : g_tokens;
    #pragma unroll
    for (int r=0;r<24;r++){
        int idx = tid + 256*r;
        int row = idx/96, c = idx%96;
        As[row][c] = Asrc[(rowbase+row)*96 + c];
    }
    __syncthreads();

    if (mode != 2){
        int warp = tid >> 5, lane = tid & 31;
        for (int rr=0; rr<8; rr++){
            int row = warp + 8*rr;
            float v0 = As[row][lane], v1 = As[row][lane+32], v2 = As[row][lane+64];
            float s = v0+v1+v2;
            #pragma unroll
            for (int o=16;o;o>>=1) s += __shfl_xor_sync(0xffffffffu, s, o);
            float m = s*(1.f/96.f);
            float d0=v0-m, d1=v1-m, d2=v2-m;
            float q = d0*d0 + d1*d1 + d2*d2;
            #pragma unroll
            for (int o=16;o;o>>=1) q += __shfl_xor_sync(0xffffffffu, q, o);
            float rs = rsqrtf(q*(1.f/96.f) + 1e-5f);
            if (mode == 0){
                float vd = v0*Wvis[lane] + v1*Wvis[lane+32] + v2*Wvis[lane+64];
                #pragma unroll
                for (int o=16;o;o>>=1) vd += __shfl_xor_sync(0xffffffffu, vd, o);
                if (lane==0) g_vis[rowbase+row] = sigm_(vd + bvis[0]);
            }
            float n0 = d0*rs*lng[lane]    + lnb[lane];
            float n1 = d1*rs*lng[lane+32] + lnb[lane+32];
            float n2 = d2*rs*lng[lane+64] + lnb[lane+64];
            As[row][lane]=n0; As[row][lane+32]=n1; As[row][lane+64]=n2;
            if (mode == 0){
                float* tp = g_tokens + (rowbase+row)*96;
                tp[lane]=n0; tp[lane+32]=n1; tp[lane+64]=n2;
            }
        }
        __syncthreads();
    }

    float acc[4][6];
    #pragma unroll
    for (int i=0;i<4;i++)
        #pragma unroll
        for (int j=0;j<6;j++) acc[i][j]=0.f;

    for (int kc=0;kc<3;kc++){
        #pragma unroll
        for (int r=0;r<12;r++){
            int idx = tid + 256*r;
            int kk = idx/96, j = idx%96;
            Bs[kk][j] = W[(kc*32+kk)*wstride + colbase + j];
        }
        __syncthreads();
        #pragma unroll
        for (int kk=0;kk<32;kk++){
            float bv[6], av[4];
            #pragma unroll
            for (int j=0;j<6;j++) bv[j] = Bs[kk][tx + 16*j];
            #pragma unroll
            for (int i=0;i<4;i++) av[i] = As[ty + 16*i][kc*32+kk];
            #pragma unroll
            for (int i=0;i<4;i++)
                #pragma unroll
                for (int j=0;j<6;j++) acc[i][j] = fmaf(av[i], bv[j], acc[i][j]);
        }
        __syncthreads();
    }

    #pragma unroll
    for (int i=0;i<4;i++)
        #pragma unroll
        for (int j=0;j<6;j++){
            int row = rowbase + ty + 16*i;
            int dl  = tx + 16*j;
            float v = acc[i][j];
            if (mode == 0)      g_gate[row*96 + dl] = sigm_(v + bgate[dl]);
            else if (mode == 1) g_xz[row*192 + colbase + dl] = v;
            else                g_tokens[row*96 + dl] += v * g_gate[row*96 + dl];
        }
}

// ---------------- 4) causal depthwise conv1d (k=3, left pad 2) + silu ----------------
__global__ void k_conv(const float* __restrict__ cw){
    int idx = blockIdx.x*blockDim.x + threadIdx.x;
    int d = idx % DI;
    int bt = idx / DI;
    int t = bt % NT; int b = bt / NT;
    const float* xin = g_xz + (b*NT)*192 + d;
    float v = xin[t*192] * cw[d*3+2];
    if (t>=1) v = fmaf(xin[(t-1)*192], cw[d*3+1], v);
    if (t>=2) v = fmaf(xin[(t-2)*192], cw[d*3+0], v);
    g_xs[idx] = silu_(v);
}

// ---------------- 5) proj (96->38) + dt = softplus(dt_raw @ W_dt + b_dt) ----------------
__global__ void k_projdt(const float* __restrict__ Wx, const float* __restrict__ Wdt,
                         const float* __restrict__ bdt){
    __shared__ float xsr[16][97];
    __shared__ float Wxs[96][39];
    __shared__ float pr[16][40];
    int tid = threadIdx.x;
    int tokbase = blockIdx.x * 16;
    for (int idx=tid; idx<16*96; idx+=128){
        int tok = idx/96, c = idx%96;
        xsr[tok][c] = g_xs[(tokbase+tok)*96 + c];
    }
    for (int idx=tid; idx<96*38; idx+=128){
        int k = idx/38, j = idx%38;
        Wxs[k][j] = Wx[idx];
    }
    __syncthreads();
    for (int idx=tid; idx<16*38; idx+=128){
        int tok = idx/38, j = idx%38;
        float a = 0.f;
        #pragma unroll 8
        for (int k=0;k<96;k++) a = fmaf(xsr[tok][k], Wxs[k][j], a);
        pr[tok][j] = a;
        g_proj[(tokbase+tok)*38 + j] = a;
    }
    __syncthreads();
    for (int idx=tid; idx<16*96; idx+=128){
        int tok = idx/96, d = idx%96;
        float a = bdt[d];
        #pragma unroll
        for (int r=0;r<6;r++) a = fmaf(pr[tok][r], Wdt[r*96+d], a);
        g_dt[(tokbase+tok)*96 + d] = softplus_(a);
    }
}

// ---------------- 6) selective scan (half-warp per d: 16 state lanes) ----------------
__global__ void k_scan(const float* __restrict__ Alog, const float* __restrict__ Dp){
    int b    = blockIdx.x >> 1;
    int half = blockIdx.x & 1;
    int w    = threadIdx.x >> 5;
    int lane = threadIdx.x & 31;
    int sub  = lane >> 4;
    int s    = lane & 15;
    int d    = half*48 + w*2 + sub;

    float Aval = -__expf(Alog[d*DS + s]);
    float Dd   = Dp[d];
    float h = 0.f;

    const float* dtp  = g_dt   + b*NT*DI + d;
    const float* xsp  = g_xs   + b*NT*DI + d;
    const float* prj  = g_proj + b*NT*38;
    const float* zp   = g_xz   + b*NT*192 + 96 + d;
    const float* visp = g_vis  + b*NT;
    float*       yo   = g_yg   + b*NT*DI + d;

    #pragma unroll 4
    for (int t=0; t<NT; t++){
        float dt = dtp[t*DI];
        float xs = xsp[t*DI];
        float Bv = prj[t*38 + 6  + s];
        float Cv = prj[t*38 + 22 + s];
        float dA = __expf(dt * Aval);
        h = fmaf(dA, h, dt*xs*Bv);
        float yp = h * Cv;
        yp += __shfl_xor_sync(0xffffffffu, yp, 1);
        yp += __shfl_xor_sync(0xffffffffu, yp, 2);
        yp += __shfl_xor_sync(0xffffffffu, yp, 4);
        yp += __shfl_xor_sync(0xffffffffu, yp, 8);
        if (s == 0){
            float z   = zp[t*192];
            float vis = visp[t];
            yo[t*DI] = (yp + Dd*xs) * silu_(z) * vis;
        }
    }
}

// ---------------- 7) heads: depthwise 3x3 + BN + silu + three matvecs ----------------
__global__ void k_final(const float* __restrict__ hd,
                        const float* __restrict__ bng, const float* __restrict__ bnb,
                        const float* __restrict__ bnm, const float* __restrict__ bnv,
                        const float* __restrict__ Wheat, const float* __restrict__ bheat,
                        const float* __restrict__ Woff,  const float* __restrict__ boff,
                        const float* __restrict__ Wsize, const float* __restrict__ bsize,
                        float* __restrict__ out){
    __shared__ float fr[3][HP][97];
    __shared__ float gs[HP][97];
    int tid = threadIdx.x;
    int b = blockIdx.x / HP;
    int h = blockIdx.x % HP;

    for (int idx=tid; idx<3*HP*96; idx+=128){
        int r = idx/(HP*96);
        int rem = idx - r*HP*96;
        int wq = rem/96, d = rem%96;
        int hh = h - 1 + r;
        fr[r][wq][d] = (hh>=0 && hh<HP) ? g_tokens[(b*NT + hh*HP + wq)*DM + d] : 0.f;
    }
    __syncthreads();

    for (int idx=tid; idx<HP*96; idx+=128){
        int wq = idx/96, d = idx%96;
        float a = 0.f;
        #pragma unroll
        for (int i=0;i<3;i++)
            #pragma unroll
            for (int j=0;j<3;j++){
                int ww = wq - 1 + j;
                if (ww>=0 && ww<HP) a = fmaf(fr[i][ww][d], hd[d*9 + i*3 + j], a);
            }
        a = (a - bnm[d]) * rsqrtf(bnv[d] + 1e-5f);
        gs[wq][d] = silu_(a*bng[d] + bnb[d]);
    }
    __syncthreads();

    const int HEAT_OFF = 0;
    const int OFF_OFF  = NB*5*NT;            // 184320
    const int SIZE_OFF = OFF_OFF + NB*2*NT;  // 258048
    for (int idx=tid; idx<HP*9; idx+=128){
        int wq = idx/9, o = idx%9;
        if (o < 5){
            float a = bheat[o];
            #pragma unroll 8
            for (int d=0; d<96; d++) a = fmaf(gs[wq][d], Wheat[o*96+d], a);
            out[HEAT_OFF + ((b*5+o)*HP + h)*HP + wq] = a;
        } else if (o < 7){
            int oo = o-5;
            float a = boff[oo];
            #pragma unroll 8
            for (int d=0; d<96; d++) a = fmaf(fr[1][wq][d], Woff[oo*96+d], a);
            out[OFF_OFF + ((b*2+oo)*HP + h)*HP + wq] = a;
        } else {
            int oo = o-7;
            float a = bsize[oo];
            #pragma unroll 8
            for (int d=0; d<96; d++) a = fmaf(fr[1][wq][d], Wsize[oo*96+d], a);
            out[SIZE_OFF + ((b*2+oo)*HP + h)*HP + wq] = a;
        }
    }
}

// ---------------- launch ----------------
extern "C" void kernel_launch(void* const* d_in, const int* in_sizes, int n_in,
                              void* d_out, int out_size){
    const float* x      = (const float*)d_in[0];
    const float* W_pe   = (const float*)d_in[1];
    const float* b_pe   = (const float*)d_in[2];
    const float* W_vis  = (const float*)d_in[3];
    const float* b_vis  = (const float*)d_in[4];
    const float* dn_g   = (const float*)d_in[5];
    const float* dn_b   = (const float*)d_in[6];
    const float* W_gate = (const float*)d_in[7];
    const float* b_gate = (const float*)d_in[8];
    const float* ln_g   = (const float*)d_in[9];
    const float* ln_b   = (const float*)d_in[10];
    const float* W_in   = (const float*)d_in[11];
    const float* conv_w = (const float*)d_in[12];
    const float* W_xprj = (const float*)d_in[13];
    const float* W_dt   = (const float*)d_in[14];
    const float* b_dt   = (const float*)d_in[15];
    const float* A_log  = (const float*)d_in[16];
    const float* Dp     = (const float*)d_in[17];
    const float* W_out  = (const float*)d_in[18];
    const float* hd_dw  = (const float*)d_in[19];
    const float* bn_g   = (const float*)d_in[20];
    const float* bn_b   = (const float*)d_in[21];
    const float* bn_m   = (const float*)d_in[22];
    const float* bn_v   = (const float*)d_in[23];
    const float* W_heat = (const float*)d_in[24];
    const float* b_heat = (const float*)d_in[25];
    const float* W_off  = (const float*)d_in[26];
    const float* b_off  = (const float*)d_in[27];
    const float* W_size = (const float*)d_in[28];
    const float* b_size = (const float*)d_in[29];
    float* out = (float*)d_out;

    k_blur_h<<<NPIX/256, 256>>>(x);
    k_blur_v<<<NPIX/256, 256>>>(x);
    k_patch<<<NR/64, 256>>>(W_pe, b_pe);

    // vis + dn-LN(tokens) + norm_gate
    k_rowgemm<<<dim3(NR/64,1), 256>>>(0, W_gate, 96, dn_g, dn_b, W_vis, b_vis, b_gate);

    for (int rep=0; rep<4; rep++){
        k_rowgemm<<<dim3(NR/64,2), 256>>>(1, W_in, 192, ln_g, ln_b, nullptr, nullptr, nullptr);
        k_conv<<<(NR*DI)/256, 256>>>(conv_w);
        k_projdt<<<NR/16, 128>>>(W_xprj, W_dt, b_dt);
        k_scan<<<2*NB, 768>>>(A_log, Dp);
        k_rowgemm<<<dim3(NR/64,1), 256>>>(2, W_out, 96, nullptr, nullptr, nullptr, nullptr, nullptr);
    }

    k_final<<<NB*HP, 128>>>(hd_dw, bn_g, bn_b, bn_m, bn_v,
                            W_heat, b_heat, W_off, b_off, W_size, b_size, out);
}

// round 3
// speedup vs baseline: 1.4069x; 1.4069x over previous
#include <cuda_runtime.h>
#include <math.h>

#define NB   64
#define IMG  384
#define CIN  3
#define PS   16
#define DM   96
#define DS   16
#define DI   96
#define HP   24
#define NT   576
#define NR   (NB*NT)          // 36864 token rows
#define NPIX (NB*CIN*IMG*IMG) // 28311552

// ---------------- scratch (device globals; no allocs allowed) ----------------
static __device__ float g_tmp[NPIX];        // horizontal blur sums
static __device__ float g_xl[NPIX];         // preprocessed image, PATCH-MAJOR [gp][768]
static __device__ float g_WpeT[768*96];     // transposed patch weights [k][d]
static __device__ float g_tokens[NR*DM];
static __device__ float g_vis[NR];
static __device__ float g_gate[NR*DM];
static __device__ float g_xin[NR*DI];       // pre-conv x branch
static __device__ float g_zg[NR*DI];        // silu(z)*vis
static __device__ float g_xs[NR*DI];
static __device__ float g_bc[NR*32];        // B(16) | C(16)
static __device__ float g_dt[NR*DI];
static __device__ float g_yg[NR*DI];

__device__ __forceinline__ float sigm_(float x){ return 1.f/(1.f+__expf(-x)); }
__device__ __forceinline__ float silu_(float x){ return x/(1.f+__expf(-x)); }
__device__ __forceinline__ float softplus_(float x){ return (x>20.f)? x : log1pf(__expf(x)); }

// ---- packed fp32x2 helpers (Blackwell FFMA2 path, PTX-only) ----
typedef unsigned long long u64;
__device__ __forceinline__ void ffma2(u64 &d, u64 a, u64 b){
    asm("fma.rn.f32x2 %0, %1, %2, %3;" : "=l"(d) : "l"(a), "l"(b), "l"(d));
}
__device__ __forceinline__ u64 pack2(float x, float y){
    u64 r;
    asm("mov.b64 %0, {%1, %2};" : "=l"(r) : "r"(__float_as_uint(x)), "r"(__float_as_uint(y)));
    return r;
}
__device__ __forceinline__ float2 unpack2(u64 v){
    unsigned lo, hi;
    asm("mov.b64 {%0, %1}, %2;" : "=r"(lo), "=r"(hi) : "l"(v));
    return make_float2(__uint_as_float(lo), __uint_as_float(hi));
}

// ---------------- 0) transpose W_pe once ----------------
__global__ void k_wt(const float* __restrict__ Wpe){
    int idx = blockIdx.x*blockDim.x + threadIdx.x;
    if (idx < 768*96){
        int k = idx/96, d = idx%96;
        g_WpeT[idx] = Wpe[d*768 + k];
    }
}

// ---------------- 1) separable 5x5 box blur + log contrast ----------------
__global__ void k_blur_h(const float* __restrict__ x){
    int idx = blockIdx.x*blockDim.x + threadIdx.x;
    int xx  = idx % IMG;
    const float* row = x + (idx - xx);
    float s = 0.f;
    #pragma unroll
    for (int d=-2; d<=2; d++){ int c = xx+d; if (c>=0 && c<IMG) s += row[c]; }
    g_tmp[idx] = s;
}

// writes preprocessed value into PATCH-MAJOR layout for the patch GEMM
__global__ void k_blur_v(const float* __restrict__ x){
    int idx = blockIdx.x*blockDim.x + threadIdx.x;
    int xx  = idx % IMG;
    int y   = (idx/IMG) % IMG;
    int bc  = idx/(IMG*IMG);
    float s = 0.f;
    #pragma unroll
    for (int d=-2; d<=2; d++){
        int yy = y+d;
        if (yy>=0 && yy<IMG) s += g_tmp[(bc*IMG+yy)*IMG + xx];
    }
    float bl = s*(1.f/25.f);
    float xv = x[idx];
    float v  = log1pf(fmaxf(xv,0.f)) - log1pf(fmaxf(bl,0.f));
    int b = bc/3, c = bc%3;
    int gp  = b*NT + (y>>4)*HP + (xx>>4);
    int col = c*256 + (y&15)*16 + (xx&15);
    g_xl[gp*768 + col] = v;
}

// ---------------- 2) patch embed GEMM: [36864 x 768] @ [768 x 96] ----------------
// 128 threads, 64 rows x 96 cols per block, thread tile 8r x 6c (3 f32x2 pairs)
__global__ void k_patch(const float* __restrict__ bpe){
    __shared__ __align__(16) float As[64][64];
    __shared__ __align__(16) float Bs[64][96];
    int tid = threadIdx.x;
    int tx = tid & 15, ty = tid >> 4;       // ty 0..7
    int rowbase = blockIdx.x * 64;
    int tx6 = tx*6;

    u64 acc[8][3];
    #pragma unroll
    for (int i=0;i<8;i++){ acc[i][0]=0ull; acc[i][1]=0ull; acc[i][2]=0ull; }

    const float4* Xg = reinterpret_cast<const float4*>(g_xl);
    const float4* Wg = reinterpret_cast<const float4*>(g_WpeT);
    float4* As4 = reinterpret_cast<float4*>(&As[0][0]);
    float4* Bs4 = reinterpret_cast<float4*>(&Bs[0][0]);

    for (int kc=0; kc<12; kc++){
        #pragma unroll
        for (int r=0;r<8;r++){
            int idx = tid + 128*r;          // < 1024
            int row = idx >> 4, c4 = idx & 15;
            As4[idx] = Xg[(rowbase+row)*192 + kc*16 + c4];
        }
        #pragma unroll
        for (int r=0;r<12;r++){
            int idx = tid + 128*r;          // < 1536
            int kk = idx/24, c4 = idx%24;
            Bs4[idx] = Wg[(kc*64+kk)*24 + c4];
        }
        __syncthreads();
        #pragma unroll 8
        for (int kk=0;kk<64;kk++){
            const u64* bp = reinterpret_cast<const u64*>(&Bs[kk][tx6]);
            u64 b0 = bp[0], b1 = bp[1], b2 = bp[2];
            #pragma unroll
            for (int i=0;i<8;i++){
                float a = As[ty + 8*i][kk];
                u64 ap = pack2(a, a);
                ffma2(acc[i][0], ap, b0);
                ffma2(acc[i][1], ap, b1);
                ffma2(acc[i][2], ap, b2);
            }
        }
        __syncthreads();
    }
    #pragma unroll
    for (int i=0;i<8;i++){
        int row = rowbase + ty + 8*i;
        #pragma unroll
        for (int j=0;j<3;j++){
            float2 v = unpack2(acc[i][j]);
            int c = tx6 + 2*j;
            g_tokens[row*DM + c]   = v.x + bpe[c];
            g_tokens[row*DM + c+1] = v.y + bpe[c+1];
        }
    }
}

// ---------------- 3) row GEMM with fused LN + epilogues ----------------
// MODE 0: raw tokens -> vis ; LN(dn) written back ; gate = sigmoid(LN @ W_gate + b)
// MODE 1: LN(ln)(tokens) @ W_in ; y==0 -> g_xin ; y==1 -> g_zg = silu(z)*vis
// MODE 2: g_yg @ W_out ; tokens += out * gate
template<int MODE>
__global__ void k_rowgemm(const float* __restrict__ W, int wstride,
                          const float* __restrict__ lng, const float* __restrict__ lnb,
                          const float* __restrict__ Wvis, const float* __restrict__ bvis,
                          const float* __restrict__ bgate){
    __shared__ __align__(16) float As[64][96];
    __shared__ __align__(16) float Bs[32][96];
    int tid = threadIdx.x;
    int tx = tid & 15, ty = tid >> 4;       // ty 0..7
    int rowbase = blockIdx.x * 64;
    int colbase = blockIdx.y * 96;
    int tx6 = tx*6;

    const float* Asrc = (MODE==2) ? g_yg : g_tokens;
    const float4* Ag = reinterpret_cast<const float4*>(Asrc + rowbase*96);
    float4* As4 = reinterpret_cast<float4*>(&As[0][0]);
    float4* Bs4 = reinterpret_cast<float4*>(&Bs[0][0]);
    #pragma unroll
    for (int r=0;r<12;r++) As4[tid + 128*r] = Ag[tid + 128*r];
    __syncthreads();

    if (MODE != 2){
        int warp = tid >> 5, lane = tid & 31;
        for (int rr=0; rr<16; rr++){
            int row = warp*16 + rr;
            float v0 = As[row][lane], v1 = As[row][lane+32], v2 = As[row][lane+64];
            float s = v0+v1+v2;
            #pragma unroll
            for (int o=16;o;o>>=1) s += __shfl_xor_sync(0xffffffffu, s, o);
            float m = s*(1.f/96.f);
            float d0=v0-m, d1=v1-m, d2=v2-m;
            float q = d0*d0 + d1*d1 + d2*d2;
            #pragma unroll
            for (int o=16;o;o>>=1) q += __shfl_xor_sync(0xffffffffu, q, o);
            float rs = rsqrtf(q*(1.f/96.f) + 1e-5f);
            if (MODE == 0){
                float vd = v0*Wvis[lane] + v1*Wvis[lane+32] + v2*Wvis[lane+64];
                #pragma unroll
                for (int o=16;o;o>>=1) vd += __shfl_xor_sync(0xffffffffu, vd, o);
                if (lane==0) g_vis[rowbase+row] = sigm_(vd + bvis[0]);
            }
            float n0 = d0*rs*lng[lane]    + lnb[lane];
            float n1 = d1*rs*lng[lane+32] + lnb[lane+32];
            float n2 = d2*rs*lng[lane+64] + lnb[lane+64];
            As[row][lane]=n0; As[row][lane+32]=n1; As[row][lane+64]=n2;
            if (MODE == 0){
                float* tp = g_tokens + (rowbase+row)*96;
                tp[lane]=n0; tp[lane+32]=n1; tp[lane+64]=n2;
            }
        }
    }

    u64 acc[8][3];
    #pragma unroll
    for (int i=0;i<8;i++){ acc[i][0]=0ull; acc[i][1]=0ull; acc[i][2]=0ull; }

    for (int kc=0;kc<3;kc++){
        __syncthreads();
        #pragma unroll
        for (int r=0;r<6;r++){
            int idx = tid + 128*r;          // < 768
            int kk = idx/24, c4 = idx%24;
            Bs4[idx] = *reinterpret_cast<const float4*>(W + (kc*32+kk)*wstride + colbase + c4*4);
        }
        __syncthreads();
        #pragma unroll 8
        for (int kk=0;kk<32;kk++){
            const u64* bp = reinterpret_cast<const u64*>(&Bs[kk][tx6]);
            u64 b0 = bp[0], b1 = bp[1], b2 = bp[2];
            int kidx = kc*32 + kk;
            #pragma unroll
            for (int i=0;i<8;i++){
                float a = As[ty + 8*i][kidx];
                u64 ap = pack2(a, a);
                ffma2(acc[i][0], ap, b0);
                ffma2(acc[i][1], ap, b1);
                ffma2(acc[i][2], ap, b2);
            }
        }
    }

    #pragma unroll
    for (int i=0;i<8;i++){
        int row = rowbase + ty + 8*i;
        float visr = (MODE==1) ? g_vis[row] : 0.f;
        #pragma unroll
        for (int j=0;j<3;j++){
            float2 v = unpack2(acc[i][j]);
            int c = tx6 + 2*j;
            if (MODE == 0){
                g_gate[row*96 + c]   = sigm_(v.x + bgate[c]);
                g_gate[row*96 + c+1] = sigm_(v.y + bgate[c+1]);
            } else if (MODE == 1){
                if (colbase == 0){
                    g_xin[row*96 + c]   = v.x;
                    g_xin[row*96 + c+1] = v.y;
                } else {
                    g_zg[row*96 + c]   = silu_(v.x)*visr;
                    g_zg[row*96 + c+1] = silu_(v.y)*visr;
                }
            } else {
                g_tokens[row*96 + c]   += v.x * g_gate[row*96 + c];
                g_tokens[row*96 + c+1] += v.y * g_gate[row*96 + c+1];
            }
        }
    }
}

// ---------------- 4) fused conv1d+silu + proj + dt ----------------
// block = 32 tokens of one batch, 128 threads
__global__ void k_cpd(const float* __restrict__ cw,
                      const float* __restrict__ Wx, const float* __restrict__ Wdt,
                      const float* __restrict__ bdt){
    __shared__ float xin_s[34][96];
    __shared__ float xs_s[32][96];
    __shared__ float Wxs[96*38];
    __shared__ float pr_dt[32][8];
    __shared__ float cws[3*96];
    int tid = threadIdx.x;
    int tb  = blockIdx.x * 32;              // global token-row base
    int tt0 = tb % NT;                      // local (per-batch) start

    // load xin rows tt0-2 .. tt0+31
    for (int idx=tid; idx<34*96; idx+=128){
        int r = idx/96, d = idx%96;
        int t = tt0 - 2 + r;
        xin_s[r][d] = (t >= 0) ? g_xin[(tb - tt0 + t)*96 + d] : 0.f;
    }
    for (int idx=tid; idx<96*38; idx+=128) Wxs[idx] = Wx[idx];
    if (tid < 96){
        cws[tid] = cw[tid*3+0]; cws[96+tid] = cw[tid*3+1]; cws[192+tid] = cw[tid*3+2];
    }
    __syncthreads();

    // conv + silu
    for (int idx=tid; idx<32*96; idx+=128){
        int l = idx/96, d = idx%96;
        float v = xin_s[l][d]*cws[d] + xin_s[l+1][d]*cws[96+d] + xin_s[l+2][d]*cws[192+d];
        v = silu_(v);
        xs_s[l][d] = v;
        g_xs[(tb+l)*96 + d] = v;
    }
    __syncthreads();

    // proj: [32 x 96] @ [96 x 38]
    for (int idx=tid; idx<32*38; idx+=128){
        int l = idx/38, j = idx%38;
        float a = 0.f;
        #pragma unroll 8
        for (int k=0;k<96;k++) a = fmaf(xs_s[l][k], Wxs[k*38+j], a);
        if (j < 6) pr_dt[l][j] = a;
        else       g_bc[(tb+l)*32 + (j-6)] = a;
    }
    __syncthreads();

    // dt = softplus(dt_raw @ W_dt + b_dt)
    for (int idx=tid; idx<32*96; idx+=128){
        int l = idx/96, d = idx%96;
        float a = bdt[d];
        #pragma unroll
        for (int r=0;r<6;r++) a = fmaf(pr_dt[l][r], Wdt[r*96+d], a);
        g_dt[(tb+l)*96 + d] = softplus_(a);
    }
}

// ---------------- 5) selective scan (half-warp per d: 16 state lanes) ----------------
__global__ void k_scan(const float* __restrict__ Alog, const float* __restrict__ Dp){
    int b    = blockIdx.x >> 1;
    int half = blockIdx.x & 1;
    int w    = threadIdx.x >> 5;
    int lane = threadIdx.x & 31;
    int sub  = lane >> 4;
    int s    = lane & 15;
    int d    = half*48 + w*2 + sub;

    float Aval = -__expf(Alog[d*DS + s]);
    float Dd   = Dp[d];
    float h = 0.f;

    const float* dtp = g_dt + b*NT*DI + d;
    const float* xsp = g_xs + b*NT*DI + d;
    const float* bcp = g_bc + b*NT*32;
    const float* zgp = g_zg + b*NT*DI + d;
    float*       yo  = g_yg + b*NT*DI + d;

    #pragma unroll 4
    for (int t=0; t<NT; t++){
        float dt = dtp[t*DI];
        float xs = xsp[t*DI];
        float Bv = bcp[t*32 + s];
        float Cv = bcp[t*32 + 16 + s];
        float dA = __expf(dt * Aval);
        h = fmaf(dA, h, dt*xs*Bv);
        float yp = h * Cv;
        yp += __shfl_xor_sync(0xffffffffu, yp, 1);
        yp += __shfl_xor_sync(0xffffffffu, yp, 2);
        yp += __shfl_xor_sync(0xffffffffu, yp, 4);
        yp += __shfl_xor_sync(0xffffffffu, yp, 8);
        if (s == 0){
            yo[t*DI] = fmaf(Dd, xs, yp) * zgp[t*DI];
        }
    }
}

// ---------------- 6) heads: depthwise 3x3 + BN + silu + three matvecs ----------------
__global__ void k_final(const float* __restrict__ hd,
                        const float* __restrict__ bng, const float* __restrict__ bnb,
                        const float* __restrict__ bnm, const float* __restrict__ bnv,
                        const float* __restrict__ Wheat, const float* __restrict__ bheat,
                        const float* __restrict__ Woff,  const float* __restrict__ boff,
                        const float* __restrict__ Wsize, const float* __restrict__ bsize,
                        float* __restrict__ out){
    __shared__ float fr[3][HP][97];
    __shared__ float gs[HP][97];
    int tid = threadIdx.x;
    int b = blockIdx.x / HP;
    int h = blockIdx.x % HP;

    for (int idx=tid; idx<3*HP*96; idx+=128){
        int r = idx/(HP*96);
        int rem = idx - r*HP*96;
        int wq = rem/96, d = rem%96;
        int hh = h - 1 + r;
        fr[r][wq][d] = (hh>=0 && hh<HP) ? g_tokens[(b*NT + hh*HP + wq)*DM + d] : 0.f;
    }
    __syncthreads();

    for (int idx=tid; idx<HP*96; idx+=128){
        int wq = idx/96, d = idx%96;
        float a = 0.f;
        #pragma unroll
        for (int i=0;i<3;i++)
            #pragma unroll
            for (int j=0;j<3;j++){
                int ww = wq - 1 + j;
                if (ww>=0 && ww<HP) a = fmaf(fr[i][ww][d], hd[d*9 + i*3 + j], a);
            }
        a = (a - bnm[d]) * rsqrtf(bnv[d] + 1e-5f);
        gs[wq][d] = silu_(a*bng[d] + bnb[d]);
    }
    __syncthreads();

    const int HEAT_OFF = 0;
    const int OFF_OFF  = NB*5*NT;
    const int SIZE_OFF = OFF_OFF + NB*2*NT;
    for (int idx=tid; idx<HP*9; idx+=128){
        int wq = idx/9, o = idx%9;
        if (o < 5){
            float a = bheat[o];
            #pragma unroll 8
            for (int d=0; d<96; d++) a = fmaf(gs[wq][d], Wheat[o*96+d], a);
            out[HEAT_OFF + ((b*5+o)*HP + h)*HP + wq] = a;
        } else if (o < 7){
            int oo = o-5;
            float a = boff[oo];
            #pragma unroll 8
            for (int d=0; d<96; d++) a = fmaf(fr[1][wq][d], Woff[oo*96+d], a);
            out[OFF_OFF + ((b*2+oo)*HP + h)*HP + wq] = a;
        } else {
            int oo = o-7;
            float a = bsize[oo];
            #pragma unroll 8
            for (int d=0; d<96; d++) a = fmaf(fr[1][wq][d], Wsize[oo*96+d], a);
            out[SIZE_OFF + ((b*2+oo)*HP + h)*HP + wq] = a;
        }
    }
}

// ---------------- launch ----------------
extern "C" void kernel_launch(void* const* d_in, const int* in_sizes, int n_in,
                              void* d_out, int out_size){
    const float* x      = (const float*)d_in[0];
    const float* W_pe   = (const float*)d_in[1];
    const float* b_pe   = (const float*)d_in[2];
    const float* W_vis  = (const float*)d_in[3];
    const float* b_vis  = (const float*)d_in[4];
    const float* dn_g   = (const float*)d_in[5];
    const float* dn_b   = (const float*)d_in[6];
    const float* W_gate = (const float*)d_in[7];
    const float* b_gate = (const float*)d_in[8];
    const float* ln_g   = (const float*)d_in[9];
    const float* ln_b   = (const float*)d_in[10];
    const float* W_in   = (const float*)d_in[11];
    const float* conv_w = (const float*)d_in[12];
    const float* W_xprj = (const float*)d_in[13];
    const float* W_dt   = (const float*)d_in[14];
    const float* b_dt   = (const float*)d_in[15];
    const float* A_log  = (const float*)d_in[16];
    const float* Dp     = (const float*)d_in[17];
    const float* W_out  = (const float*)d_in[18];
    const float* hd_dw  = (const float*)d_in[19];
    const float* bn_g   = (const float*)d_in[20];
    const float* bn_b   = (const float*)d_in[21];
    const float* bn_m   = (const float*)d_in[22];
    const float* bn_v   = (const float*)d_in[23];
    const float* W_heat = (const float*)d_in[24];
    const float* b_heat = (const float*)d_in[25];
    const float* W_off  = (const float*)d_in[26];
    const float* b_off  = (const float*)d_in[27];
    const float* W_size = (const float*)d_in[28];
    const float* b_size = (const float*)d_in[29];
    float* out = (float*)d_out;

    k_wt<<<(768*96+255)/256, 256>>>(W_pe);
    k_blur_h<<<NPIX/256, 256>>>(x);
    k_blur_v<<<NPIX/256, 256>>>(x);
    k_patch<<<NR/64, 128>>>(b_pe);

    k_rowgemm<0><<<dim3(NR/64,1), 128>>>(W_gate, 96, dn_g, dn_b, W_vis, b_vis, b_gate);

    for (int rep=0; rep<4; rep++){
        k_rowgemm<1><<<dim3(NR/64,2), 128>>>(W_in, 192, ln_g, ln_b, nullptr, nullptr, nullptr);
        k_cpd<<<NR/32, 128>>>(conv_w, W_xprj, W_dt, b_dt);
        k_scan<<<2*NB, 768>>>(A_log, Dp);
        k_rowgemm<2><<<dim3(NR/64,1), 128>>>(W_out, 96, nullptr, nullptr, nullptr, nullptr, nullptr);
    }

    k_final<<<NB*HP, 128>>>(hd_dw, bn_g, bn_b, bn_m, bn_v,
                            W_heat, b_heat, W_off, b_off, W_size, b_size, out);
}